// round 1
// baseline (speedup 1.0000x reference)
#include <cuda_runtime.h>
#include <cuda_bf16.h>

#define N_NODES   50000
#define N_EDGES   800000
#define IN_CH     128
#define HID       64
#define N_GRAPHS  256
#define N_CLASSES 10

// ---------------- scratch (static device globals; no allocation) ------------
__device__ float g_deg[N_NODES];
__device__ float g_dinv[N_NODES];
__device__ float g_hw[N_NODES * 64];      // X@W result (both layers)
__device__ float g_agg[N_NODES * 64];     // scatter accumulator / layer output
__device__ float g_pooled[N_GRAPHS * 64];
__device__ float g_counts[N_GRAPHS];

// ---------------- small utility kernels -------------------------------------
__global__ void k_zero(float* __restrict__ p, int n) {
    int i = blockIdx.x * blockDim.x + threadIdx.x;
    if (i < n) p[i] = 0.0f;
}

__global__ void k_deg(const int* __restrict__ dst, float* __restrict__ deg) {
    int e = blockIdx.x * blockDim.x + threadIdx.x;
    if (e < N_EDGES) atomicAdd(&deg[dst[e]], 1.0f);
}

__global__ void k_dinv(const float* __restrict__ deg, float* __restrict__ dinv) {
    int i = blockIdx.x * blockDim.x + threadIdx.x;
    if (i < N_NODES) dinv[i] = rsqrtf(deg[i] + 1.0f);
}

// ---------------- GEMM: C[N x 64] = A[N x FIN] @ W[FIN x 64] ----------------
// 64-row tile per block, 256 threads, 4x4 register micro-tile per thread.
// A tile staged transposed in shared memory (padded stride 68 -> conflict-free
// float4 reads, 16B-aligned rows). W streamed via __ldg float4 (L1-resident).
template <int FIN>
__global__ __launch_bounds__(256) void k_gemm(const float* __restrict__ A,
                                              const float* __restrict__ W,
                                              float* __restrict__ C) {
    __shared__ __align__(16) float As[FIN][68];
    const int t  = threadIdx.x;
    const int m0 = blockIdx.x * 64;

    // load A tile transposed: As[k][m]
    for (int idx = t; idx < 64 * FIN; idx += 256) {
        int m = idx / FIN;
        int k = idx - m * FIN;
        int row = m0 + m;
        As[k][m] = (row < N_NODES) ? A[(size_t)row * FIN + k] : 0.0f;
    }
    __syncthreads();

    const int ty = t >> 4;   // 0..15 -> rows ty*4..ty*4+3
    const int tx = t & 15;   // 0..15 -> cols tx*4..tx*4+3

    float acc[4][4];
#pragma unroll
    for (int i = 0; i < 4; i++)
#pragma unroll
        for (int j = 0; j < 4; j++) acc[i][j] = 0.0f;

#pragma unroll 4
    for (int k = 0; k < FIN; k++) {
        float4 a = *(const float4*)&As[k][ty * 4];
        float4 w = __ldg((const float4*)&W[k * 64 + tx * 4]);
        acc[0][0] += a.x * w.x; acc[0][1] += a.x * w.y; acc[0][2] += a.x * w.z; acc[0][3] += a.x * w.w;
        acc[1][0] += a.y * w.x; acc[1][1] += a.y * w.y; acc[1][2] += a.y * w.z; acc[1][3] += a.y * w.w;
        acc[2][0] += a.z * w.x; acc[2][1] += a.z * w.y; acc[2][2] += a.z * w.z; acc[2][3] += a.z * w.w;
        acc[3][0] += a.w * w.x; acc[3][1] += a.w * w.y; acc[3][2] += a.w * w.z; acc[3][3] += a.w * w.w;
    }

#pragma unroll
    for (int i = 0; i < 4; i++) {
        int row = m0 + ty * 4 + i;
        if (row < N_NODES) {
            float4 o = make_float4(acc[i][0], acc[i][1], acc[i][2], acc[i][3]);
            *(float4*)&C[(size_t)row * 64 + tx * 4] = o;
        }
    }
}

// ---------------- edge gather + vectorized scatter-add -----------------------
// 16 threads per edge; leader lane loads indices + norm, shfl-broadcast.
// Grid sized exactly: N_EDGES*16 threads, 256/block -> 50000 blocks (no remainder).
__global__ __launch_bounds__(256) void k_edge(const int* __restrict__ src,
                                              const int* __restrict__ dst,
                                              const float* __restrict__ dinv,
                                              const float* __restrict__ h,
                                              float* __restrict__ agg) {
    int tid  = blockIdx.x * blockDim.x + threadIdx.x;
    int e    = tid >> 4;
    int lane = threadIdx.x & 31;
    int sub  = lane & 15;

    int s = 0, d = 0;
    float norm = 0.0f;
    if (sub == 0) {
        s = src[e];
        d = dst[e];
        norm = dinv[s] * dinv[d];
    }
    int leader = lane & 16;  // 0 or 16
    s    = __shfl_sync(0xFFFFFFFFu, s, leader);
    d    = __shfl_sync(0xFFFFFFFFu, d, leader);
    norm = __shfl_sync(0xFFFFFFFFu, norm, leader);

    float4 v = *(const float4*)&h[(size_t)s * 64 + sub * 4];
    float4 m = make_float4(v.x * norm, v.y * norm, v.z * norm, v.w * norm);
    atomicAdd((float4*)&agg[(size_t)d * 64 + sub * 4], m);
}

// ---------------- combine: agg += h*dinv^2 + b (+ReLU) -----------------------
template <bool RELU>
__global__ void k_combine(const float* __restrict__ hw,
                          const float* __restrict__ dinv,
                          const float* __restrict__ bias,
                          float* __restrict__ agg) {
    int idx = blockIdx.x * blockDim.x + threadIdx.x;
    if (idx < N_NODES * 64) {
        int n = idx >> 6;
        int c = idx & 63;
        float di = dinv[n];
        float v = agg[idx] + hw[idx] * di * di + bias[c];
        agg[idx] = RELU ? fmaxf(v, 0.0f) : v;
    }
}

// ---------------- pooling ----------------------------------------------------
__global__ void k_counts(const int* __restrict__ batch, float* __restrict__ counts) {
    int i = blockIdx.x * blockDim.x + threadIdx.x;
    if (i < N_NODES) atomicAdd(&counts[batch[i]], 1.0f);
}

__global__ __launch_bounds__(256) void k_pool(const int* __restrict__ batch,
                                              const float* __restrict__ h,
                                              float* __restrict__ pooled) {
    int tid = blockIdx.x * blockDim.x + threadIdx.x;  // exactly N_NODES*16
    int n   = tid >> 4;
    if (n >= N_NODES) return;
    int sub = tid & 15;
    int g = batch[n];
    float4 v = *(const float4*)&h[(size_t)n * 64 + sub * 4];
    atomicAdd((float4*)&pooled[(size_t)g * 64 + sub * 4], v);
}

// ---------------- final: out = (pooled/count) @ Wl + bl ----------------------
__global__ void k_final(const float* __restrict__ pooled,
                        const float* __restrict__ counts,
                        const float* __restrict__ Wl,
                        const float* __restrict__ bl,
                        float* __restrict__ out) {
    int tid = blockIdx.x * blockDim.x + threadIdx.x;
    if (tid >= N_GRAPHS * N_CLASSES) return;
    int g = tid / N_CLASSES;
    int j = tid - g * N_CLASSES;
    float s = 0.0f;
#pragma unroll
    for (int c = 0; c < 64; c++) s += pooled[g * 64 + c] * Wl[c * N_CLASSES + j];
    float cnt = fmaxf(counts[g], 1.0f);
    out[tid] = s / cnt + bl[j];
}

// ---------------- host launch -------------------------------------------------
static float* sym_addr(const void* sym) {
    void* p = nullptr;
    cudaGetSymbolAddress(&p, sym);
    return (float*)p;
}

extern "C" void kernel_launch(void* const* d_in, const int* in_sizes, int n_in,
                              void* d_out, int out_size) {
    const float* x     = (const float*)d_in[0];
    const int*   ei    = (const int*)d_in[1];
    const int*   srcp  = ei;
    const int*   dstp  = ei + N_EDGES;
    // d_in[2] = edge_attr (unused by reference math)
    const int*   batch = (const int*)d_in[3];
    const float* W1 = (const float*)d_in[4];
    const float* b1 = (const float*)d_in[5];
    const float* W2 = (const float*)d_in[6];
    const float* b2 = (const float*)d_in[7];
    const float* Wl = (const float*)d_in[8];
    const float* bl = (const float*)d_in[9];
    float* out = (float*)d_out;

    static float* p_deg    = nullptr;
    static float* p_dinv   = nullptr;
    static float* p_hw     = nullptr;
    static float* p_agg    = nullptr;
    static float* p_pooled = nullptr;
    static float* p_counts = nullptr;
    if (!p_deg) {
        p_deg    = sym_addr(g_deg);
        p_dinv   = sym_addr(g_dinv);
        p_hw     = sym_addr(g_hw);
        p_agg    = sym_addr(g_agg);
        p_pooled = sym_addr(g_pooled);
        p_counts = sym_addr(g_counts);
    }

    const int B = 256;
    // degrees + normalization
    k_zero<<<(N_NODES + B - 1) / B, B>>>(p_deg, N_NODES);
    k_deg<<<(N_EDGES + B - 1) / B, B>>>(dstp, p_deg);
    k_dinv<<<(N_NODES + B - 1) / B, B>>>(p_deg, p_dinv);

    // ---- layer 1 ----
    k_gemm<IN_CH><<<(N_NODES + 63) / 64, B>>>(x, W1, p_hw);
    k_zero<<<(N_NODES * 64 + B - 1) / B, B>>>(p_agg, N_NODES * 64);
    k_edge<<<(N_EDGES * 16) / B, B>>>(srcp, dstp, p_dinv, p_hw, p_agg);
    k_combine<true><<<(N_NODES * 64 + B - 1) / B, B>>>(p_hw, p_dinv, b1, p_agg);

    // ---- layer 2 ----
    k_gemm<HID><<<(N_NODES + 63) / 64, B>>>(p_agg, W2, p_hw);
    // note: k_gemm reads p_agg before the zero below (stream-ordered)
    k_zero<<<(N_NODES * 64 + B - 1) / B, B>>>(p_agg, N_NODES * 64);
    k_edge<<<(N_EDGES * 16) / B, B>>>(srcp, dstp, p_dinv, p_hw, p_agg);
    k_combine<false><<<(N_NODES * 64 + B - 1) / B, B>>>(p_hw, p_dinv, b2, p_agg);

    // ---- pooling + classifier ----
    k_zero<<<(N_GRAPHS * 64 + B - 1) / B, B>>>(p_pooled, N_GRAPHS * 64);
    k_zero<<<(N_GRAPHS + B - 1) / B, B>>>(p_counts, N_GRAPHS);
    k_counts<<<(N_NODES + B - 1) / B, B>>>(batch, p_counts);
    k_pool<<<(N_NODES * 16 + B - 1) / B, B>>>(batch, p_agg, p_pooled);
    k_final<<<(N_GRAPHS * N_CLASSES + B - 1) / B, B>>>(p_pooled, p_counts, Wl, bl, out);
}

// round 2
// speedup vs baseline: 1.1232x; 1.1232x over previous
#include <cuda_runtime.h>
#include <cuda_bf16.h>

#define N_NODES   50000
#define N_EDGES   800000
#define IN_CH     128
#define HID       64
#define N_GRAPHS  256
#define N_CLASSES 10

// ---------------- scratch (static device globals; no allocation) ------------
__device__ float g_deg[N_NODES];
__device__ float g_dinv[N_NODES];
__device__ float g_norm[N_EDGES];
__device__ float g_hw[N_NODES * 64];       // X@W result (both layers, reused)
__device__ float g_agg1[N_NODES * 64];     // layer-1 accumulator / output
__device__ float g_agg2[N_NODES * 64];     // layer-2 accumulator / output
__device__ float g_pooled[N_GRAPHS * 64];
__device__ float g_counts[N_GRAPHS];

// ---------------- small utility kernels -------------------------------------
__global__ void k_zero(float* __restrict__ p, int n) {
    int i = blockIdx.x * blockDim.x + threadIdx.x;
    if (i < n) p[i] = 0.0f;
}

__global__ void k_deg(const int* __restrict__ dst, float* __restrict__ deg) {
    int e = blockIdx.x * blockDim.x + threadIdx.x;
    if (e < N_EDGES) atomicAdd(&deg[dst[e]], 1.0f);
}

__global__ void k_dinv(const float* __restrict__ deg, float* __restrict__ dinv) {
    int i = blockIdx.x * blockDim.x + threadIdx.x;
    if (i < N_NODES) dinv[i] = rsqrtf(deg[i] + 1.0f);
}

__global__ void k_norm(const int* __restrict__ src, const int* __restrict__ dst,
                       const float* __restrict__ dinv, float* __restrict__ norm) {
    int e = blockIdx.x * blockDim.x + threadIdx.x;
    if (e < N_EDGES) norm[e] = dinv[src[e]] * dinv[dst[e]];
}

// ---------------- fused GEMM + self-loop init --------------------------------
// C[N x 64] = A[N x FIN] @ W[FIN x 64]
// Writes H = C and AGG = C * dinv^2 + bias (so no separate zero/combine pass).
// RELU_IN applies ReLU to A on load (used for layer 2 reading layer-1 output).
// 64-row tile / block, 256 threads, 4x4 register micro-tile.
__device__ __forceinline__ float4 f4fma(float a, float4 b, float4 c) {
    c.x = fmaf(a, b.x, c.x); c.y = fmaf(a, b.y, c.y);
    c.z = fmaf(a, b.z, c.z); c.w = fmaf(a, b.w, c.w);
    return c;
}

template <int FIN, bool RELU_IN>
__global__ __launch_bounds__(256) void k_gemm_fused(
    const float* __restrict__ A, const float* __restrict__ W,
    const float* __restrict__ dinv, const float* __restrict__ bias,
    float* __restrict__ H, float* __restrict__ AGG) {
    // row-major A tile, padded to keep float4 alignment; reads are broadcast.
    __shared__ __align__(16) float As[64][FIN + 4];
    const int t  = threadIdx.x;
    const int m0 = blockIdx.x * 64;
    constexpr int V4 = FIN / 4;

    // stage A tile (coalesced float4 global reads, conflict-free STS.128)
    for (int idx = t; idx < 64 * V4; idx += 256) {
        int m  = idx / V4;
        int kk = idx - m * V4;
        int row = m0 + m;
        float4 v = make_float4(0.f, 0.f, 0.f, 0.f);
        if (row < N_NODES) {
            v = __ldg((const float4*)(A + (size_t)row * FIN) + kk);
            if (RELU_IN) {
                v.x = fmaxf(v.x, 0.f); v.y = fmaxf(v.y, 0.f);
                v.z = fmaxf(v.z, 0.f); v.w = fmaxf(v.w, 0.f);
            }
        }
        *(float4*)&As[m][kk * 4] = v;
    }
    __syncthreads();

    const int ty = t >> 4;   // 0..15 -> rows ty*4..ty*4+3
    const int tx = t & 15;   // 0..15 -> cols tx*4..tx*4+3

    float4 c0 = make_float4(0.f, 0.f, 0.f, 0.f);
    float4 c1 = c0, c2 = c0, c3 = c0;

    const float4* __restrict__ Wv = (const float4*)W;  // Wv[k*16 + tx]

#pragma unroll 8
    for (int k = 0; k < FIN; k += 4) {
        float4 a0 = *(const float4*)&As[ty * 4 + 0][k];
        float4 a1 = *(const float4*)&As[ty * 4 + 1][k];
        float4 a2 = *(const float4*)&As[ty * 4 + 2][k];
        float4 a3 = *(const float4*)&As[ty * 4 + 3][k];
        float4 w0 = __ldg(Wv + (k + 0) * 16 + tx);
        float4 w1 = __ldg(Wv + (k + 1) * 16 + tx);
        float4 w2 = __ldg(Wv + (k + 2) * 16 + tx);
        float4 w3 = __ldg(Wv + (k + 3) * 16 + tx);
        c0 = f4fma(a0.x, w0, c0); c0 = f4fma(a0.y, w1, c0);
        c0 = f4fma(a0.z, w2, c0); c0 = f4fma(a0.w, w3, c0);
        c1 = f4fma(a1.x, w0, c1); c1 = f4fma(a1.y, w1, c1);
        c1 = f4fma(a1.z, w2, c1); c1 = f4fma(a1.w, w3, c1);
        c2 = f4fma(a2.x, w0, c2); c2 = f4fma(a2.y, w1, c2);
        c2 = f4fma(a2.z, w2, c2); c2 = f4fma(a2.w, w3, c2);
        c3 = f4fma(a3.x, w0, c3); c3 = f4fma(a3.y, w1, c3);
        c3 = f4fma(a3.z, w2, c3); c3 = f4fma(a3.w, w3, c3);
    }

    float4 bb = __ldg((const float4*)bias + tx);
    float4 cc[4] = {c0, c1, c2, c3};
#pragma unroll
    for (int i = 0; i < 4; i++) {
        int row = m0 + ty * 4 + i;
        if (row < N_NODES) {
            float di = dinv[row];
            float s = di * di;
            float4 ci = cc[i];
            *(float4*)(H + (size_t)row * 64 + tx * 4) = ci;
            float4 ai = make_float4(fmaf(ci.x, s, bb.x), fmaf(ci.y, s, bb.y),
                                    fmaf(ci.z, s, bb.z), fmaf(ci.w, s, bb.w));
            *(float4*)(AGG + (size_t)row * 64 + tx * 4) = ai;
        }
    }
}

// ---------------- edge gather + vectorized scatter-add -----------------------
// 16 threads per edge; leader lane loads indices + norm, shfl-broadcast.
// Grid exact: N_EDGES*16 threads / 256 = 50000 blocks.
__global__ __launch_bounds__(256) void k_edge(const int* __restrict__ src,
                                              const int* __restrict__ dst,
                                              const float* __restrict__ norm,
                                              const float* __restrict__ h,
                                              float* __restrict__ agg) {
    int tid  = blockIdx.x * blockDim.x + threadIdx.x;
    int e    = tid >> 4;
    int lane = threadIdx.x & 31;
    int sub  = lane & 15;

    int s = 0, d = 0;
    float nm = 0.0f;
    if (sub == 0) {
        s  = src[e];
        d  = dst[e];
        nm = norm[e];
    }
    int leader = lane & 16;  // 0 or 16
    s  = __shfl_sync(0xFFFFFFFFu, s, leader);
    d  = __shfl_sync(0xFFFFFFFFu, d, leader);
    nm = __shfl_sync(0xFFFFFFFFu, nm, leader);

    float4 v = *(const float4*)&h[(size_t)s * 64 + sub * 4];
    float4 m = make_float4(v.x * nm, v.y * nm, v.z * nm, v.w * nm);
    atomicAdd((float4*)&agg[(size_t)d * 64 + sub * 4], m);
}

// ---------------- pooling ----------------------------------------------------
__global__ void k_counts(const int* __restrict__ batch, float* __restrict__ counts) {
    int i = blockIdx.x * blockDim.x + threadIdx.x;
    if (i < N_NODES) atomicAdd(&counts[batch[i]], 1.0f);
}

__global__ __launch_bounds__(256) void k_pool(const int* __restrict__ batch,
                                              const float* __restrict__ h,
                                              float* __restrict__ pooled) {
    int tid = blockIdx.x * blockDim.x + threadIdx.x;
    int n   = tid >> 4;
    if (n >= N_NODES) return;
    int sub = tid & 15;
    int g = batch[n];
    float4 v = *(const float4*)&h[(size_t)n * 64 + sub * 4];
    atomicAdd((float4*)&pooled[(size_t)g * 64 + sub * 4], v);
}

// ---------------- final: out = (pooled/count) @ Wl + bl ----------------------
__global__ void k_final(const float* __restrict__ pooled,
                        const float* __restrict__ counts,
                        const float* __restrict__ Wl,
                        const float* __restrict__ bl,
                        float* __restrict__ out) {
    int tid = blockIdx.x * blockDim.x + threadIdx.x;
    if (tid >= N_GRAPHS * N_CLASSES) return;
    int g = tid / N_CLASSES;
    int j = tid - g * N_CLASSES;
    float s = 0.0f;
#pragma unroll
    for (int c = 0; c < 64; c++) s += pooled[g * 64 + c] * Wl[c * N_CLASSES + j];
    float cnt = fmaxf(counts[g], 1.0f);
    out[tid] = s / cnt + bl[j];
}

// ---------------- host launch -------------------------------------------------
static float* sym_addr(const void* sym) {
    void* p = nullptr;
    cudaGetSymbolAddress(&p, sym);
    return (float*)p;
}

extern "C" void kernel_launch(void* const* d_in, const int* in_sizes, int n_in,
                              void* d_out, int out_size) {
    const float* x     = (const float*)d_in[0];
    const int*   ei    = (const int*)d_in[1];
    const int*   srcp  = ei;
    const int*   dstp  = ei + N_EDGES;
    const int*   batch = (const int*)d_in[3];
    const float* W1 = (const float*)d_in[4];
    const float* b1 = (const float*)d_in[5];
    const float* W2 = (const float*)d_in[6];
    const float* b2 = (const float*)d_in[7];
    const float* Wl = (const float*)d_in[8];
    const float* bl = (const float*)d_in[9];
    float* out = (float*)d_out;

    static float* p_deg    = nullptr;
    static float* p_dinv   = nullptr;
    static float* p_norm   = nullptr;
    static float* p_hw     = nullptr;
    static float* p_agg1   = nullptr;
    static float* p_agg2   = nullptr;
    static float* p_pooled = nullptr;
    static float* p_counts = nullptr;
    if (!p_deg) {
        p_deg    = sym_addr(g_deg);
        p_dinv   = sym_addr(g_dinv);
        p_norm   = sym_addr(g_norm);
        p_hw     = sym_addr(g_hw);
        p_agg1   = sym_addr(g_agg1);
        p_agg2   = sym_addr(g_agg2);
        p_pooled = sym_addr(g_pooled);
        p_counts = sym_addr(g_counts);
    }

    const int B = 256;
    // degrees + normalization
    k_zero<<<(N_NODES + B - 1) / B, B>>>(p_deg, N_NODES);
    k_deg<<<(N_EDGES + B - 1) / B, B>>>(dstp, p_deg);
    k_dinv<<<(N_NODES + B - 1) / B, B>>>(p_deg, p_dinv);
    k_norm<<<(N_EDGES + B - 1) / B, B>>>(srcp, dstp, p_dinv, p_norm);

    // ---- layer 1 : h1 = X@W1 ; agg1 = h1*dinv^2 + b1 ; edge scatter ----
    k_gemm_fused<IN_CH, false><<<(N_NODES + 63) / 64, B>>>(x, W1, p_dinv, b1, p_hw, p_agg1);
    k_edge<<<(N_EDGES * 16) / B, B>>>(srcp, dstp, p_norm, p_hw, p_agg1);
    // (layer-1 ReLU is applied on the A-load inside gemm2)

    // ---- layer 2 : h2 = relu(agg1)@W2 ; agg2 = h2*dinv^2 + b2 ; edge ----
    k_gemm_fused<HID, true><<<(N_NODES + 63) / 64, B>>>(p_agg1, W2, p_dinv, b2, p_hw, p_agg2);
    k_edge<<<(N_EDGES * 16) / B, B>>>(srcp, dstp, p_norm, p_hw, p_agg2);

    // ---- pooling + classifier ----
    k_zero<<<(N_GRAPHS * 64 + B - 1) / B, B>>>(p_pooled, N_GRAPHS * 64);
    k_zero<<<(N_GRAPHS + B - 1) / B, B>>>(p_counts, N_GRAPHS);
    k_counts<<<(N_NODES + B - 1) / B, B>>>(batch, p_counts);
    k_pool<<<(N_NODES * 16 + B - 1) / B, B>>>(batch, p_agg2, p_pooled);
    k_final<<<(N_GRAPHS * N_CLASSES + B - 1) / B, B>>>(p_pooled, p_counts, Wl, bl, out);
}

// round 3
// speedup vs baseline: 1.5364x; 1.3678x over previous
#include <cuda_runtime.h>
#include <cuda_bf16.h>

#define N_NODES   50000
#define N_EDGES   800000
#define IN_CH     128
#define HID       64
#define N_GRAPHS  256
#define N_CLASSES 10

#define SCAN_B    256
#define N_SCANBLK ((N_NODES + SCAN_B - 1) / SCAN_B)   // 196

// ---------------- scratch (static device globals; no allocation) ------------
__device__ int   g_deg[N_NODES];
__device__ int   g_offs[N_NODES];       // local (per-block) exclusive scan
__device__ int   g_top[N_SCANBLK];      // block-prefix
__device__ int   g_cursor[N_NODES];
__device__ float g_dinv[N_NODES];
__device__ int   g_csr_src[N_EDGES];
__device__ float g_csr_norm[N_EDGES];
__device__ float g_hw[N_NODES * 64];    // X@W result (both layers, reused)
__device__ float g_agg1[N_NODES * 64];  // layer-1 output (post ReLU)
__device__ float g_pooled[N_GRAPHS * 64];
__device__ int   g_counts[N_GRAPHS];

// ---------------- init: zero everything that needs it ------------------------
__global__ void k_init(int* __restrict__ deg, int* __restrict__ cursor,
                       float* __restrict__ pooled, int* __restrict__ counts) {
    int i = blockIdx.x * blockDim.x + threadIdx.x;
    if (i < N_NODES) { deg[i] = 0; cursor[i] = 0; }
    if (i < N_GRAPHS * 64) pooled[i] = 0.0f;
    if (i < N_GRAPHS) counts[i] = 0;
}

__global__ void k_deg(const int* __restrict__ dst, int* __restrict__ deg) {
    int e = blockIdx.x * blockDim.x + threadIdx.x;
    if (e < N_EDGES) atomicAdd(&deg[dst[e]], 1);
}

// per-block exclusive scan of deg + dinv computation
__global__ __launch_bounds__(SCAN_B) void k_scan_part(
    const int* __restrict__ deg, int* __restrict__ offs,
    int* __restrict__ part, float* __restrict__ dinv) {
    __shared__ int s[SCAN_B];
    int t = threadIdx.x;
    int i = blockIdx.x * SCAN_B + t;
    int d = (i < N_NODES) ? deg[i] : 0;
    if (i < N_NODES) dinv[i] = rsqrtf((float)d + 1.0f);
    s[t] = d;
    __syncthreads();
#pragma unroll
    for (int off = 1; off < SCAN_B; off <<= 1) {
        int x = (t >= off) ? s[t - off] : 0;
        __syncthreads();
        s[t] += x;
        __syncthreads();
    }
    if (i < N_NODES) offs[i] = s[t] - d;          // exclusive
    if (t == SCAN_B - 1) part[blockIdx.x] = s[t]; // block total
}

// scan the 196 block totals (single block)
__global__ __launch_bounds__(SCAN_B) void k_scan_top(int* __restrict__ part) {
    __shared__ int s[SCAN_B];
    int t = threadIdx.x;
    int v = (t < N_SCANBLK) ? part[t] : 0;
    s[t] = v;
    __syncthreads();
#pragma unroll
    for (int off = 1; off < SCAN_B; off <<= 1) {
        int x = (t >= off) ? s[t - off] : 0;
        __syncthreads();
        s[t] += x;
        __syncthreads();
    }
    if (t < N_SCANBLK) part[t] = s[t] - v;        // exclusive
}

// scatter edges into CSR buckets (norm fused here; absorbs old k_norm)
__global__ void k_csr(const int* __restrict__ src, const int* __restrict__ dst,
                      const int* __restrict__ offs, const int* __restrict__ top,
                      int* __restrict__ cursor, const float* __restrict__ dinv,
                      int* __restrict__ csr_src, float* __restrict__ csr_norm) {
    int e = blockIdx.x * blockDim.x + threadIdx.x;
    if (e >= N_EDGES) return;
    int s = src[e];
    int d = dst[e];
    int pos = offs[d] + top[d >> 8] + atomicAdd(&cursor[d], 1);
    csr_src[pos]  = s;
    csr_norm[pos] = dinv[s] * dinv[d];
}

// ---------------- GEMM: H[N x 64] = A[N x FIN] @ W[FIN x 64] ----------------
__device__ __forceinline__ float4 f4fma(float a, float4 b, float4 c) {
    c.x = fmaf(a, b.x, c.x); c.y = fmaf(a, b.y, c.y);
    c.z = fmaf(a, b.z, c.z); c.w = fmaf(a, b.w, c.w);
    return c;
}

template <int FIN>
__global__ __launch_bounds__(256) void k_gemm(
    const float* __restrict__ A, const float* __restrict__ W,
    float* __restrict__ H) {
    __shared__ __align__(16) float As[64][FIN + 4];
    const int t  = threadIdx.x;
    const int m0 = blockIdx.x * 64;
    constexpr int V4 = FIN / 4;

    for (int idx = t; idx < 64 * V4; idx += 256) {
        int m  = idx / V4;
        int kk = idx - m * V4;
        int row = m0 + m;
        float4 v = make_float4(0.f, 0.f, 0.f, 0.f);
        if (row < N_NODES) v = __ldg((const float4*)(A + (size_t)row * FIN) + kk);
        *(float4*)&As[m][kk * 4] = v;
    }
    __syncthreads();

    const int ty = t >> 4;
    const int tx = t & 15;

    float4 c0 = make_float4(0.f, 0.f, 0.f, 0.f);
    float4 c1 = c0, c2 = c0, c3 = c0;
    const float4* __restrict__ Wv = (const float4*)W;

#pragma unroll 8
    for (int k = 0; k < FIN; k += 4) {
        float4 a0 = *(const float4*)&As[ty * 4 + 0][k];
        float4 a1 = *(const float4*)&As[ty * 4 + 1][k];
        float4 a2 = *(const float4*)&As[ty * 4 + 2][k];
        float4 a3 = *(const float4*)&As[ty * 4 + 3][k];
        float4 w0 = __ldg(Wv + (k + 0) * 16 + tx);
        float4 w1 = __ldg(Wv + (k + 1) * 16 + tx);
        float4 w2 = __ldg(Wv + (k + 2) * 16 + tx);
        float4 w3 = __ldg(Wv + (k + 3) * 16 + tx);
        c0 = f4fma(a0.x, w0, c0); c0 = f4fma(a0.y, w1, c0);
        c0 = f4fma(a0.z, w2, c0); c0 = f4fma(a0.w, w3, c0);
        c1 = f4fma(a1.x, w0, c1); c1 = f4fma(a1.y, w1, c1);
        c1 = f4fma(a1.z, w2, c1); c1 = f4fma(a1.w, w3, c1);
        c2 = f4fma(a2.x, w0, c2); c2 = f4fma(a2.y, w1, c2);
        c2 = f4fma(a2.z, w2, c2); c2 = f4fma(a2.w, w3, c2);
        c3 = f4fma(a3.x, w0, c3); c3 = f4fma(a3.y, w1, c3);
        c3 = f4fma(a3.z, w2, c3); c3 = f4fma(a3.w, w3, c3);
    }

    float4 cc[4] = {c0, c1, c2, c3};
#pragma unroll
    for (int i = 0; i < 4; i++) {
        int row = m0 + ty * 4 + i;
        if (row < N_NODES) *(float4*)(H + (size_t)row * 64 + tx * 4) = cc[i];
    }
}

// ---------------- gather-based aggregation (no atomics on features) ----------
// 16 threads per node, thread sub owns channels [4*sub, 4*sub+4).
// agg[n] = (POOL? pool+= : write) [relu]( sum_in norm*h[src] + h[n]*dinv^2 + b )
template <bool RELU, bool POOL>
__global__ __launch_bounds__(256) void k_agg(
    const int* __restrict__ deg, const int* __restrict__ offs,
    const int* __restrict__ top, const float* __restrict__ dinv,
    const int* __restrict__ csr_src, const float* __restrict__ csr_norm,
    const float* __restrict__ h, const float* __restrict__ bias,
    float* __restrict__ out, const int* __restrict__ batch,
    float* __restrict__ pooled) {
    int tid = blockIdx.x * blockDim.x + threadIdx.x;   // exactly N_NODES*16
    int n   = tid >> 4;
    int sub = tid & 15;
    if (n >= N_NODES) return;

    int beg = offs[n] + top[n >> 8];
    int end = beg + deg[n];

    // self-loop contribution + bias
    float di = dinv[n];
    float s2 = di * di;
    float4 hv = *(const float4*)&h[(size_t)n * 64 + sub * 4];
    float4 bb = __ldg((const float4*)bias + sub);
    float4 acc = make_float4(fmaf(hv.x, s2, bb.x), fmaf(hv.y, s2, bb.y),
                             fmaf(hv.z, s2, bb.z), fmaf(hv.w, s2, bb.w));

    int j = beg;
    for (; j + 2 <= end; j += 2) {
        int   s0 = csr_src[j];
        int   s1 = csr_src[j + 1];
        float n0 = csr_norm[j];
        float n1 = csr_norm[j + 1];
        float4 v0 = *(const float4*)&h[(size_t)s0 * 64 + sub * 4];
        float4 v1 = *(const float4*)&h[(size_t)s1 * 64 + sub * 4];
        acc = f4fma(n0, v0, acc);
        acc = f4fma(n1, v1, acc);
    }
    if (j < end) {
        int   s0 = csr_src[j];
        float n0 = csr_norm[j];
        float4 v0 = *(const float4*)&h[(size_t)s0 * 64 + sub * 4];
        acc = f4fma(n0, v0, acc);
    }

    if (RELU) {
        acc.x = fmaxf(acc.x, 0.f); acc.y = fmaxf(acc.y, 0.f);
        acc.z = fmaxf(acc.z, 0.f); acc.w = fmaxf(acc.w, 0.f);
    }

    if (POOL) {
        int g = batch[n];
        atomicAdd((float4*)&pooled[(size_t)g * 64 + sub * 4], acc);
    } else {
        *(float4*)&out[(size_t)n * 64 + sub * 4] = acc;
    }
}

// ---------------- pooling counts + classifier --------------------------------
__global__ void k_counts(const int* __restrict__ batch, int* __restrict__ counts) {
    int i = blockIdx.x * blockDim.x + threadIdx.x;
    if (i < N_NODES) atomicAdd(&counts[batch[i]], 1);
}

__global__ void k_final(const float* __restrict__ pooled,
                        const int* __restrict__ counts,
                        const float* __restrict__ Wl,
                        const float* __restrict__ bl,
                        float* __restrict__ out) {
    int tid = blockIdx.x * blockDim.x + threadIdx.x;
    if (tid >= N_GRAPHS * N_CLASSES) return;
    int g = tid / N_CLASSES;
    int j = tid - g * N_CLASSES;
    float s = 0.0f;
#pragma unroll
    for (int c = 0; c < 64; c++) s += pooled[g * 64 + c] * Wl[c * N_CLASSES + j];
    float cnt = fmaxf((float)counts[g], 1.0f);
    out[tid] = s / cnt + bl[j];
}

// ---------------- host launch -------------------------------------------------
template <typename T>
static T* sym_addr(const void* sym) {
    void* p = nullptr;
    cudaGetSymbolAddress(&p, sym);
    return (T*)p;
}

extern "C" void kernel_launch(void* const* d_in, const int* in_sizes, int n_in,
                              void* d_out, int out_size) {
    const float* x     = (const float*)d_in[0];
    const int*   ei    = (const int*)d_in[1];
    const int*   srcp  = ei;
    const int*   dstp  = ei + N_EDGES;
    const int*   batch = (const int*)d_in[3];
    const float* W1 = (const float*)d_in[4];
    const float* b1 = (const float*)d_in[5];
    const float* W2 = (const float*)d_in[6];
    const float* b2 = (const float*)d_in[7];
    const float* Wl = (const float*)d_in[8];
    const float* bl = (const float*)d_in[9];
    float* out = (float*)d_out;

    static int*   p_deg    = nullptr;
    static int*   p_offs   = nullptr;
    static int*   p_top    = nullptr;
    static int*   p_cursor = nullptr;
    static float* p_dinv   = nullptr;
    static int*   p_csrs   = nullptr;
    static float* p_csrn   = nullptr;
    static float* p_hw     = nullptr;
    static float* p_agg1   = nullptr;
    static float* p_pooled = nullptr;
    static int*   p_counts = nullptr;
    if (!p_deg) {
        p_deg    = sym_addr<int>(g_deg);
        p_offs   = sym_addr<int>(g_offs);
        p_top    = sym_addr<int>(g_top);
        p_cursor = sym_addr<int>(g_cursor);
        p_dinv   = sym_addr<float>(g_dinv);
        p_csrs   = sym_addr<int>(g_csr_src);
        p_csrn   = sym_addr<float>(g_csr_norm);
        p_hw     = sym_addr<float>(g_hw);
        p_agg1   = sym_addr<float>(g_agg1);
        p_pooled = sym_addr<float>(g_pooled);
        p_counts = sym_addr<int>(g_counts);
    }

    const int B = 256;

    // ---- CSR build ----
    k_init<<<(N_NODES + B - 1) / B, B>>>(p_deg, p_cursor, p_pooled, p_counts);
    k_deg<<<(N_EDGES + B - 1) / B, B>>>(dstp, p_deg);
    k_scan_part<<<N_SCANBLK, SCAN_B>>>(p_deg, p_offs, p_top, p_dinv);
    k_scan_top<<<1, SCAN_B>>>(p_top);
    k_csr<<<(N_EDGES + B - 1) / B, B>>>(srcp, dstp, p_offs, p_top, p_cursor,
                                        p_dinv, p_csrs, p_csrn);
    k_counts<<<(N_NODES + B - 1) / B, B>>>(batch, p_counts);

    // ---- layer 1 ----
    k_gemm<IN_CH><<<(N_NODES + 63) / 64, B>>>(x, W1, p_hw);
    k_agg<true, false><<<(N_NODES * 16 + B - 1) / B, B>>>(
        p_deg, p_offs, p_top, p_dinv, p_csrs, p_csrn, p_hw, b1,
        p_agg1, nullptr, nullptr);

    // ---- layer 2 (aggregate fused with mean-pool scatter) ----
    k_gemm<HID><<<(N_NODES + 63) / 64, B>>>(p_agg1, W2, p_hw);
    k_agg<false, true><<<(N_NODES * 16 + B - 1) / B, B>>>(
        p_deg, p_offs, p_top, p_dinv, p_csrs, p_csrn, p_hw, b2,
        nullptr, batch, p_pooled);

    // ---- classifier ----
    k_final<<<(N_GRAPHS * N_CLASSES + B - 1) / B, B>>>(p_pooled, p_counts, Wl, bl, out);
}

// round 5
// speedup vs baseline: 1.5603x; 1.0156x over previous
#include <cuda_runtime.h>
#include <cuda_fp16.h>
#include <cuda_bf16.h>

#define N_NODES   50000
#define N_EDGES   800000
#define IN_CH     128
#define HID       64
#define N_GRAPHS  256
#define N_CLASSES 10

#define SCAN_B    256
#define N_SCANBLK ((N_NODES + SCAN_B - 1) / SCAN_B)   // 196

// ---------------- scratch (static device globals; no allocation) ------------
__device__ int    g_deg[N_NODES];
__device__ int    g_offs[N_NODES];       // global exclusive offsets
__device__ int    g_cursor[N_NODES];
__device__ int    g_total;               // running base for block offsets
__device__ float  g_dinv[N_NODES];
__device__ int2   g_csr[N_EDGES];        // {src, norm-as-bits}
__device__ __half g_hw[N_NODES * 64];    // X@W result, fp16 (both layers)
__device__ float  g_agg1[N_NODES * 64];  // layer-1 output (post ReLU, fp32)
__device__ float  g_pooled[N_GRAPHS * 64];
__device__ int    g_counts[N_GRAPHS];

// ---------------- init: zero everything that needs it ------------------------
__global__ void k_init(int* __restrict__ deg, int* __restrict__ cursor,
                       float* __restrict__ pooled, int* __restrict__ counts,
                       int* __restrict__ total) {
    int i = blockIdx.x * blockDim.x + threadIdx.x;
    if (i < N_NODES) { deg[i] = 0; cursor[i] = 0; }
    if (i < N_GRAPHS * 64) pooled[i] = 0.0f;
    if (i < N_GRAPHS) counts[i] = 0;
    if (i == 0) *total = 0;
}

// edge-degree histogram + batch counts in one launch
__global__ void k_deg_counts(const int* __restrict__ dst, int* __restrict__ deg,
                             const int* __restrict__ batch, int* __restrict__ counts) {
    int i = blockIdx.x * blockDim.x + threadIdx.x;
    if (i < N_EDGES) atomicAdd(&deg[dst[i]], 1);
    if (i < N_NODES) atomicAdd(&counts[batch[i]], 1);
}

// fused scan: per-block exclusive scan + atomic block base + dinv.
// Bucket ordering across blocks is arbitrary but irrelevant (only contiguity
// and sizing matter for the gather).
__global__ __launch_bounds__(SCAN_B) void k_scan(
    const int* __restrict__ deg, int* __restrict__ offs,
    int* __restrict__ total, float* __restrict__ dinv) {
    __shared__ int s[SCAN_B];
    __shared__ int base;
    int t = threadIdx.x;
    int i = blockIdx.x * SCAN_B + t;
    int d = (i < N_NODES) ? deg[i] : 0;
    if (i < N_NODES) dinv[i] = rsqrtf((float)d + 1.0f);
    s[t] = d;
    __syncthreads();
#pragma unroll
    for (int off = 1; off < SCAN_B; off <<= 1) {
        int x = (t >= off) ? s[t - off] : 0;
        __syncthreads();
        s[t] += x;
        __syncthreads();
    }
    if (t == SCAN_B - 1) base = atomicAdd(total, s[t]);
    __syncthreads();
    if (i < N_NODES) offs[i] = base + s[t] - d;   // exclusive + block base
}

// scatter edges into CSR buckets with packed (src, norm)
__global__ void k_csr(const int* __restrict__ src, const int* __restrict__ dst,
                      const int* __restrict__ offs, int* __restrict__ cursor,
                      const float* __restrict__ dinv, int2* __restrict__ csr) {
    int e = blockIdx.x * blockDim.x + threadIdx.x;
    if (e >= N_EDGES) return;
    int s = src[e];
    int d = dst[e];
    int pos = offs[d] + atomicAdd(&cursor[d], 1);
    csr[pos] = make_int2(s, __float_as_int(dinv[s] * dinv[d]));
}

// ---------------- GEMM: H[N x 64](fp16) = A[N x FIN](fp32) @ W[FIN x 64] ----
__device__ __forceinline__ float4 f4fma(float a, float4 b, float4 c) {
    c.x = fmaf(a, b.x, c.x); c.y = fmaf(a, b.y, c.y);
    c.z = fmaf(a, b.z, c.z); c.w = fmaf(a, b.w, c.w);
    return c;
}

template <int FIN>
__global__ __launch_bounds__(256) void k_gemm(
    const float* __restrict__ A, const float* __restrict__ W,
    __half* __restrict__ H) {
    __shared__ __align__(16) float As[64][FIN + 4];
    const int t  = threadIdx.x;
    const int m0 = blockIdx.x * 64;
    constexpr int V4 = FIN / 4;

    for (int idx = t; idx < 64 * V4; idx += 256) {
        int m  = idx / V4;
        int kk = idx - m * V4;
        int row = m0 + m;
        float4 v = make_float4(0.f, 0.f, 0.f, 0.f);
        if (row < N_NODES) v = __ldg((const float4*)(A + (size_t)row * FIN) + kk);
        *(float4*)&As[m][kk * 4] = v;
    }
    __syncthreads();

    const int ty = t >> 4;
    const int tx = t & 15;

    float4 c0 = make_float4(0.f, 0.f, 0.f, 0.f);
    float4 c1 = c0, c2 = c0, c3 = c0;
    const float4* __restrict__ Wv = (const float4*)W;

#pragma unroll 8
    for (int k = 0; k < FIN; k += 4) {
        float4 a0 = *(const float4*)&As[ty * 4 + 0][k];
        float4 a1 = *(const float4*)&As[ty * 4 + 1][k];
        float4 a2 = *(const float4*)&As[ty * 4 + 2][k];
        float4 a3 = *(const float4*)&As[ty * 4 + 3][k];
        float4 w0 = __ldg(Wv + (k + 0) * 16 + tx);
        float4 w1 = __ldg(Wv + (k + 1) * 16 + tx);
        float4 w2 = __ldg(Wv + (k + 2) * 16 + tx);
        float4 w3 = __ldg(Wv + (k + 3) * 16 + tx);
        c0 = f4fma(a0.x, w0, c0); c0 = f4fma(a0.y, w1, c0);
        c0 = f4fma(a0.z, w2, c0); c0 = f4fma(a0.w, w3, c0);
        c1 = f4fma(a1.x, w0, c1); c1 = f4fma(a1.y, w1, c1);
        c1 = f4fma(a1.z, w2, c1); c1 = f4fma(a1.w, w3, c1);
        c2 = f4fma(a2.x, w0, c2); c2 = f4fma(a2.y, w1, c2);
        c2 = f4fma(a2.z, w2, c2); c2 = f4fma(a2.w, w3, c2);
        c3 = f4fma(a3.x, w0, c3); c3 = f4fma(a3.y, w1, c3);
        c3 = f4fma(a3.z, w2, c3); c3 = f4fma(a3.w, w3, c3);
    }

    float4 cc[4] = {c0, c1, c2, c3};
#pragma unroll
    for (int i = 0; i < 4; i++) {
        int row = m0 + ty * 4 + i;
        if (row < N_NODES) {
            __half2 h0 = __floats2half2_rn(cc[i].x, cc[i].y);
            __half2 h1 = __floats2half2_rn(cc[i].z, cc[i].w);
            uint2 packed = make_uint2(*(unsigned*)&h0, *(unsigned*)&h1);
            *(uint2*)(H + (size_t)row * 64 + tx * 4) = packed;
        }
    }
}

// ---------------- gather aggregation (fp16 gather, fp32 accumulate) ----------
// 8 threads per node; lane sub owns channels [8*sub, 8*sub+8) = 16 B.
template <bool RELU, bool POOL>
__global__ __launch_bounds__(256) void k_agg(
    const int* __restrict__ deg, const int* __restrict__ offs,
    const float* __restrict__ dinv, const int2* __restrict__ csr,
    const __half* __restrict__ h, const float* __restrict__ bias,
    float* __restrict__ out, const int* __restrict__ batch,
    float* __restrict__ pooled) {
    int tid = blockIdx.x * blockDim.x + threadIdx.x;
    int n   = tid >> 3;
    int sub = tid & 7;
    if (n >= N_NODES) return;

    int beg = offs[n];
    int end = beg + deg[n];

    float acc[8];
    // self-loop + bias
    {
        float di = dinv[n];
        float s2 = di * di;
        uint4 raw = *(const uint4*)(h + (size_t)n * 64 + sub * 8);
        float2 f0 = __half22float2(*(__half2*)&raw.x);
        float2 f1 = __half22float2(*(__half2*)&raw.y);
        float2 f2 = __half22float2(*(__half2*)&raw.z);
        float2 f3 = __half22float2(*(__half2*)&raw.w);
        float4 bb0 = __ldg((const float4*)bias + sub * 2);
        float4 bb1 = __ldg((const float4*)bias + sub * 2 + 1);
        acc[0] = fmaf(f0.x, s2, bb0.x); acc[1] = fmaf(f0.y, s2, bb0.y);
        acc[2] = fmaf(f1.x, s2, bb0.z); acc[3] = fmaf(f1.y, s2, bb0.w);
        acc[4] = fmaf(f2.x, s2, bb1.x); acc[5] = fmaf(f2.y, s2, bb1.y);
        acc[6] = fmaf(f3.x, s2, bb1.z); acc[7] = fmaf(f3.y, s2, bb1.w);
    }

    int j = beg;
    for (; j + 2 <= end; j += 2) {
        int2 e0 = csr[j];
        int2 e1 = csr[j + 1];
        float n0 = __int_as_float(e0.y);
        float n1 = __int_as_float(e1.y);
        uint4 r0 = *(const uint4*)(h + (size_t)e0.x * 64 + sub * 8);
        uint4 r1 = *(const uint4*)(h + (size_t)e1.x * 64 + sub * 8);
        {
            float2 f0 = __half22float2(*(__half2*)&r0.x);
            float2 f1 = __half22float2(*(__half2*)&r0.y);
            float2 f2 = __half22float2(*(__half2*)&r0.z);
            float2 f3 = __half22float2(*(__half2*)&r0.w);
            acc[0] = fmaf(n0, f0.x, acc[0]); acc[1] = fmaf(n0, f0.y, acc[1]);
            acc[2] = fmaf(n0, f1.x, acc[2]); acc[3] = fmaf(n0, f1.y, acc[3]);
            acc[4] = fmaf(n0, f2.x, acc[4]); acc[5] = fmaf(n0, f2.y, acc[5]);
            acc[6] = fmaf(n0, f3.x, acc[6]); acc[7] = fmaf(n0, f3.y, acc[7]);
        }
        {
            float2 f0 = __half22float2(*(__half2*)&r1.x);
            float2 f1 = __half22float2(*(__half2*)&r1.y);
            float2 f2 = __half22float2(*(__half2*)&r1.z);
            float2 f3 = __half22float2(*(__half2*)&r1.w);
            acc[0] = fmaf(n1, f0.x, acc[0]); acc[1] = fmaf(n1, f0.y, acc[1]);
            acc[2] = fmaf(n1, f1.x, acc[2]); acc[3] = fmaf(n1, f1.y, acc[3]);
            acc[4] = fmaf(n1, f2.x, acc[4]); acc[5] = fmaf(n1, f2.y, acc[5]);
            acc[6] = fmaf(n1, f3.x, acc[6]); acc[7] = fmaf(n1, f3.y, acc[7]);
        }
    }
    if (j < end) {
        int2 e0 = csr[j];
        float n0 = __int_as_float(e0.y);
        uint4 r0 = *(const uint4*)(h + (size_t)e0.x * 64 + sub * 8);
        float2 f0 = __half22float2(*(__half2*)&r0.x);
        float2 f1 = __half22float2(*(__half2*)&r0.y);
        float2 f2 = __half22float2(*(__half2*)&r0.z);
        float2 f3 = __half22float2(*(__half2*)&r0.w);
        acc[0] = fmaf(n0, f0.x, acc[0]); acc[1] = fmaf(n0, f0.y, acc[1]);
        acc[2] = fmaf(n0, f1.x, acc[2]); acc[3] = fmaf(n0, f1.y, acc[3]);
        acc[4] = fmaf(n0, f2.x, acc[4]); acc[5] = fmaf(n0, f2.y, acc[5]);
        acc[6] = fmaf(n0, f3.x, acc[6]); acc[7] = fmaf(n0, f3.y, acc[7]);
    }

    if (RELU) {
#pragma unroll
        for (int c = 0; c < 8; c++) acc[c] = fmaxf(acc[c], 0.0f);
    }

    if (POOL) {
        int g = batch[n];
        float4 a0 = make_float4(acc[0], acc[1], acc[2], acc[3]);
        float4 a1 = make_float4(acc[4], acc[5], acc[6], acc[7]);
        atomicAdd((float4*)&pooled[(size_t)g * 64 + sub * 8], a0);
        atomicAdd((float4*)&pooled[(size_t)g * 64 + sub * 8 + 4], a1);
    } else {
        float4 a0 = make_float4(acc[0], acc[1], acc[2], acc[3]);
        float4 a1 = make_float4(acc[4], acc[5], acc[6], acc[7]);
        *(float4*)&out[(size_t)n * 64 + sub * 8] = a0;
        *(float4*)&out[(size_t)n * 64 + sub * 8 + 4] = a1;
    }
}

// ---------------- classifier --------------------------------------------------
__global__ void k_final(const float* __restrict__ pooled,
                        const int* __restrict__ counts,
                        const float* __restrict__ Wl,
                        const float* __restrict__ bl,
                        float* __restrict__ out) {
    int tid = blockIdx.x * blockDim.x + threadIdx.x;
    if (tid >= N_GRAPHS * N_CLASSES) return;
    int g = tid / N_CLASSES;
    int j = tid - g * N_CLASSES;
    float s = 0.0f;
#pragma unroll
    for (int c = 0; c < 64; c++) s += pooled[g * 64 + c] * Wl[c * N_CLASSES + j];
    float cnt = fmaxf((float)counts[g], 1.0f);
    out[tid] = s / cnt + bl[j];
}

// ---------------- host launch -------------------------------------------------
template <typename T, typename S>
static T* sym_addr(const S& sym) {
    void* p = nullptr;
    cudaGetSymbolAddress(&p, sym);
    return (T*)p;
}

extern "C" void kernel_launch(void* const* d_in, const int* in_sizes, int n_in,
                              void* d_out, int out_size) {
    const float* x     = (const float*)d_in[0];
    const int*   ei    = (const int*)d_in[1];
    const int*   srcp  = ei;
    const int*   dstp  = ei + N_EDGES;
    const int*   batch = (const int*)d_in[3];
    const float* W1 = (const float*)d_in[4];
    const float* b1 = (const float*)d_in[5];
    const float* W2 = (const float*)d_in[6];
    const float* b2 = (const float*)d_in[7];
    const float* Wl = (const float*)d_in[8];
    const float* bl = (const float*)d_in[9];
    float* out = (float*)d_out;

    static int*    p_deg    = nullptr;
    static int*    p_offs   = nullptr;
    static int*    p_cursor = nullptr;
    static int*    p_total  = nullptr;
    static float*  p_dinv   = nullptr;
    static int2*   p_csr    = nullptr;
    static __half* p_hw     = nullptr;
    static float*  p_agg1   = nullptr;
    static float*  p_pooled = nullptr;
    static int*    p_counts = nullptr;
    if (!p_deg) {
        p_deg    = sym_addr<int>(g_deg);
        p_offs   = sym_addr<int>(g_offs);
        p_cursor = sym_addr<int>(g_cursor);
        p_total  = sym_addr<int>(g_total);
        p_dinv   = sym_addr<float>(g_dinv);
        p_csr    = sym_addr<int2>(g_csr);
        p_hw     = sym_addr<__half>(g_hw);
        p_agg1   = sym_addr<float>(g_agg1);
        p_pooled = sym_addr<float>(g_pooled);
        p_counts = sym_addr<int>(g_counts);
    }

    const int B = 256;

    // ---- CSR build (4 launches) ----
    k_init<<<(N_NODES + B - 1) / B, B>>>(p_deg, p_cursor, p_pooled, p_counts, p_total);
    k_deg_counts<<<(N_EDGES + B - 1) / B, B>>>(dstp, p_deg, batch, p_counts);
    k_scan<<<N_SCANBLK, SCAN_B>>>(p_deg, p_offs, p_total, p_dinv);
    k_csr<<<(N_EDGES + B - 1) / B, B>>>(srcp, dstp, p_offs, p_cursor, p_dinv, p_csr);

    // ---- layer 1 ----
    k_gemm<IN_CH><<<(N_NODES + 63) / 64, B>>>(x, W1, p_hw);
    k_agg<true, false><<<(N_NODES * 8 + B - 1) / B, B>>>(
        p_deg, p_offs, p_dinv, p_csr, p_hw, b1, p_agg1, nullptr, nullptr);

    // ---- layer 2 (aggregate fused with mean-pool scatter) ----
    k_gemm<HID><<<(N_NODES + 63) / 64, B>>>(p_agg1, W2, p_hw);
    k_agg<false, true><<<(N_NODES * 8 + B - 1) / B, B>>>(
        p_deg, p_offs, p_dinv, p_csr, p_hw, b2, nullptr, batch, p_pooled);

    // ---- classifier ----
    k_final<<<(N_GRAPHS * N_CLASSES + B - 1) / B, B>>>(p_pooled, p_counts, Wl, bl, out);
}

// round 6
// speedup vs baseline: 2.0818x; 1.3342x over previous
#include <cuda_runtime.h>
#include <cuda_fp16.h>
#include <cuda_bf16.h>
#include <mma.h>

using namespace nvcuda;

#define N_NODES   50000
#define N_EDGES   800000
#define IN_CH     128
#define HID       64
#define N_GRAPHS  256
#define N_CLASSES 10

#define SCAN_B    256
#define N_SCANBLK ((N_NODES + SCAN_B - 1) / SCAN_B)   // 196

// ---------------- scratch (static device globals; no allocation) ------------
__device__ int    g_deg[N_NODES];
__device__ int    g_offs[N_NODES];       // global exclusive offsets
__device__ int    g_cursor[N_NODES];     // running cursor (starts at offs)
__device__ int    g_total;
__device__ float  g_dinv[N_NODES];
__device__ int    g_csr[N_EDGES];        // src only; norm recomputed in agg
__device__ __half g_hw[N_NODES * 64];    // X@W result, fp16 (both layers)
__device__ __half g_agg1[N_NODES * 64];  // layer-1 output (post ReLU, fp16)
__device__ float  g_pooled[N_GRAPHS * 64];
__device__ int    g_counts[N_GRAPHS];

// ---------------- init ---------------------------------------------------------
__global__ void k_init(int* __restrict__ deg, float* __restrict__ pooled,
                       int* __restrict__ counts, int* __restrict__ total) {
    int i = blockIdx.x * blockDim.x + threadIdx.x;
    if (i < N_NODES) deg[i] = 0;
    if (i < N_GRAPHS * 64) pooled[i] = 0.0f;
    if (i < N_GRAPHS) counts[i] = 0;
    if (i == 0) *total = 0;
}

// edge-degree histogram + batch counts in one launch
__global__ void k_deg_counts(const int* __restrict__ dst, int* __restrict__ deg,
                             const int* __restrict__ batch, int* __restrict__ counts) {
    int i = blockIdx.x * blockDim.x + threadIdx.x;
    if (i < N_EDGES) atomicAdd(&deg[dst[i]], 1);
    if (i < N_NODES) atomicAdd(&counts[batch[i]], 1);
}

// fused scan: per-block exclusive scan + atomic block base + dinv + cursor init.
__global__ __launch_bounds__(SCAN_B) void k_scan(
    const int* __restrict__ deg, int* __restrict__ offs, int* __restrict__ cursor,
    int* __restrict__ total, float* __restrict__ dinv) {
    __shared__ int s[SCAN_B];
    __shared__ int base;
    int t = threadIdx.x;
    int i = blockIdx.x * SCAN_B + t;
    int d = (i < N_NODES) ? deg[i] : 0;
    if (i < N_NODES) dinv[i] = rsqrtf((float)d + 1.0f);
    s[t] = d;
    __syncthreads();
#pragma unroll
    for (int off = 1; off < SCAN_B; off <<= 1) {
        int x = (t >= off) ? s[t - off] : 0;
        __syncthreads();
        s[t] += x;
        __syncthreads();
    }
    if (t == SCAN_B - 1) base = atomicAdd(total, s[t]);
    __syncthreads();
    if (i < N_NODES) {
        int o = base + s[t] - d;
        offs[i]   = o;
        cursor[i] = o;
    }
}

// scatter: one atomic, one 4-byte store per edge
__global__ void k_csr(const int* __restrict__ src, const int* __restrict__ dst,
                      int* __restrict__ cursor, int* __restrict__ csr) {
    int e = blockIdx.x * blockDim.x + threadIdx.x;
    if (e >= N_EDGES) return;
    int s = src[e];
    int d = dst[e];
    int pos = atomicAdd(&cursor[d], 1);
    csr[pos] = s;
}

// ---------------- wmma GEMM: H[N x 64](fp16) = A[N x FIN] @ W[FIN x 64] -----
// Block: 256 threads (8 warps), 64-row tile. Warp grid 4(M) x 2(N); each warp
// computes 16x32 with two m16n16k16 fragments, fp32 accumulate.
// A converted to fp16 in smem (or loaded directly if AHALF). W fp32->fp16.
template <int FIN, bool AHALF>
__global__ __launch_bounds__(256) void k_gemm_wmma(
    const void* __restrict__ Ain, const float* __restrict__ W,
    __half* __restrict__ H) {
    constexpr int LDA = FIN + 16;
    constexpr int LDW = 64 + 16;  // 80
    constexpr int LDC = 72;
    constexpr int A_BYTES = 64 * LDA * 2;
    constexpr int W_BYTES = FIN * LDW * 2;
    constexpr int C_BYTES = 64 * LDC * 4;
    constexpr int S_BYTES = (A_BYTES + W_BYTES) > C_BYTES ? (A_BYTES + W_BYTES) : C_BYTES;
    __shared__ __align__(32) char sraw[S_BYTES];
    __half* Ah = (__half*)sraw;
    __half* Wh = (__half*)(sraw + A_BYTES);
    float*  Cs = (float*)sraw;   // aliases Ah/Wh after compute is done

    const int t  = threadIdx.x;
    const int m0 = blockIdx.x * 64;

    // stage A (fp16 in smem)
    if (AHALF) {
        const __half* A = (const __half*)Ain;
        for (int idx = t; idx < 64 * (FIN / 8); idx += 256) {
            int m  = idx / (FIN / 8);
            int kk = idx % (FIN / 8);
            int row = m0 + m;
            uint4 v = make_uint4(0u, 0u, 0u, 0u);
            if (row < N_NODES) v = *(const uint4*)(A + (size_t)row * FIN + kk * 8);
            *(uint4*)&Ah[m * LDA + kk * 8] = v;
        }
    } else {
        const float* A = (const float*)Ain;
        for (int idx = t; idx < 64 * (FIN / 4); idx += 256) {
            int m  = idx / (FIN / 4);
            int kk = idx % (FIN / 4);
            int row = m0 + m;
            float4 v = make_float4(0.f, 0.f, 0.f, 0.f);
            if (row < N_NODES) v = __ldg((const float4*)(A + (size_t)row * FIN) + kk);
            __half2 h0 = __floats2half2_rn(v.x, v.y);
            __half2 h1 = __floats2half2_rn(v.z, v.w);
            *(__half2*)&Ah[m * LDA + kk * 4]     = h0;
            *(__half2*)&Ah[m * LDA + kk * 4 + 2] = h1;
        }
    }
    // stage W (fp32 -> fp16)
    for (int idx = t; idx < FIN * 16; idx += 256) {
        int k  = idx / 16;
        int c4 = idx % 16;
        float4 v = __ldg((const float4*)(W + (size_t)k * 64) + c4);
        __half2 h0 = __floats2half2_rn(v.x, v.y);
        __half2 h1 = __floats2half2_rn(v.z, v.w);
        *(__half2*)&Wh[k * LDW + c4 * 4]     = h0;
        *(__half2*)&Wh[k * LDW + c4 * 4 + 2] = h1;
    }
    __syncthreads();

    const int wid = t >> 5;
    const int wm  = wid >> 1;   // 0..3
    const int wn  = wid & 1;    // 0..1

    wmma::fragment<wmma::accumulator, 16, 16, 16, float> c0, c1;
    wmma::fill_fragment(c0, 0.0f);
    wmma::fill_fragment(c1, 0.0f);

#pragma unroll
    for (int k = 0; k < FIN; k += 16) {
        wmma::fragment<wmma::matrix_a, 16, 16, 16, __half, wmma::row_major> a;
        wmma::load_matrix_sync(a, &Ah[(wm * 16) * LDA + k], LDA);
        wmma::fragment<wmma::matrix_b, 16, 16, 16, __half, wmma::row_major> b0, b1;
        wmma::load_matrix_sync(b0, &Wh[k * LDW + wn * 32], LDW);
        wmma::load_matrix_sync(b1, &Wh[k * LDW + wn * 32 + 16], LDW);
        wmma::mma_sync(c0, a, b0, c0);
        wmma::mma_sync(c1, a, b1, c1);
    }

    __syncthreads();   // all reads of Ah/Wh complete before aliasing as Cs
    wmma::store_matrix_sync(&Cs[(wm * 16) * LDC + wn * 32],      c0, LDC, wmma::mem_row_major);
    wmma::store_matrix_sync(&Cs[(wm * 16) * LDC + wn * 32 + 16], c1, LDC, wmma::mem_row_major);
    __syncthreads();

    // write H fp16, coalesced
    for (int idx = t; idx < 64 * 16; idx += 256) {
        int m  = idx >> 4;
        int c4 = idx & 15;
        int row = m0 + m;
        if (row < N_NODES) {
            float4 v = *(float4*)&Cs[m * LDC + c4 * 4];
            __half2 h0 = __floats2half2_rn(v.x, v.y);
            __half2 h1 = __floats2half2_rn(v.z, v.w);
            uint2 p = make_uint2(*(unsigned*)&h0, *(unsigned*)&h1);
            *(uint2*)(H + (size_t)row * 64 + c4 * 4) = p;
        }
    }
}

// ---------------- gather aggregation (fp16 gather, fp32 accumulate) ----------
// 8 threads per node; lane sub owns channels [8*sub, 8*sub+8) = 16 B.
// norm = dinv[src] * dinv[n] computed on the fly (dinv table is L2-resident).
__device__ __forceinline__ void acc_row(float acc[8], float nm, uint4 r) {
    float2 f0 = __half22float2(*(__half2*)&r.x);
    float2 f1 = __half22float2(*(__half2*)&r.y);
    float2 f2 = __half22float2(*(__half2*)&r.z);
    float2 f3 = __half22float2(*(__half2*)&r.w);
    acc[0] = fmaf(nm, f0.x, acc[0]); acc[1] = fmaf(nm, f0.y, acc[1]);
    acc[2] = fmaf(nm, f1.x, acc[2]); acc[3] = fmaf(nm, f1.y, acc[3]);
    acc[4] = fmaf(nm, f2.x, acc[4]); acc[5] = fmaf(nm, f2.y, acc[5]);
    acc[6] = fmaf(nm, f3.x, acc[6]); acc[7] = fmaf(nm, f3.y, acc[7]);
}

template <bool RELU, bool POOL>
__global__ __launch_bounds__(256) void k_agg(
    const int* __restrict__ deg, const int* __restrict__ offs,
    const float* __restrict__ dinv, const int* __restrict__ csr,
    const __half* __restrict__ h, const float* __restrict__ bias,
    __half* __restrict__ out16, const int* __restrict__ batch,
    float* __restrict__ pooled) {
    int tid = blockIdx.x * blockDim.x + threadIdx.x;
    int n   = tid >> 3;
    int sub = tid & 7;
    if (n >= N_NODES) return;

    int beg = offs[n];
    int end = beg + deg[n];
    float di = dinv[n];

    float acc[8];
    {
        float s2 = di * di;
        uint4 raw = *(const uint4*)(h + (size_t)n * 64 + sub * 8);
        float4 bb0 = __ldg((const float4*)bias + sub * 2);
        float4 bb1 = __ldg((const float4*)bias + sub * 2 + 1);
        float2 f0 = __half22float2(*(__half2*)&raw.x);
        float2 f1 = __half22float2(*(__half2*)&raw.y);
        float2 f2 = __half22float2(*(__half2*)&raw.z);
        float2 f3 = __half22float2(*(__half2*)&raw.w);
        acc[0] = fmaf(f0.x, s2, bb0.x); acc[1] = fmaf(f0.y, s2, bb0.y);
        acc[2] = fmaf(f1.x, s2, bb0.z); acc[3] = fmaf(f1.y, s2, bb0.w);
        acc[4] = fmaf(f2.x, s2, bb1.x); acc[5] = fmaf(f2.y, s2, bb1.y);
        acc[6] = fmaf(f3.x, s2, bb1.z); acc[7] = fmaf(f3.y, s2, bb1.w);
    }

    int j = beg;
    for (; j + 2 <= end; j += 2) {
        int s0 = csr[j];
        int s1 = csr[j + 1];
        float n0 = dinv[s0] * di;
        float n1 = dinv[s1] * di;
        uint4 r0 = *(const uint4*)(h + (size_t)s0 * 64 + sub * 8);
        uint4 r1 = *(const uint4*)(h + (size_t)s1 * 64 + sub * 8);
        acc_row(acc, n0, r0);
        acc_row(acc, n1, r1);
    }
    if (j < end) {
        int s0 = csr[j];
        float n0 = dinv[s0] * di;
        uint4 r0 = *(const uint4*)(h + (size_t)s0 * 64 + sub * 8);
        acc_row(acc, n0, r0);
    }

    if (RELU) {
#pragma unroll
        for (int c = 0; c < 8; c++) acc[c] = fmaxf(acc[c], 0.0f);
    }

    if (POOL) {
        int g = batch[n];
        float4 a0 = make_float4(acc[0], acc[1], acc[2], acc[3]);
        float4 a1 = make_float4(acc[4], acc[5], acc[6], acc[7]);
        atomicAdd((float4*)&pooled[(size_t)g * 64 + sub * 8], a0);
        atomicAdd((float4*)&pooled[(size_t)g * 64 + sub * 8 + 4], a1);
    } else {
        __half2 h0 = __floats2half2_rn(acc[0], acc[1]);
        __half2 h1 = __floats2half2_rn(acc[2], acc[3]);
        __half2 h2 = __floats2half2_rn(acc[4], acc[5]);
        __half2 h3 = __floats2half2_rn(acc[6], acc[7]);
        uint4 p = make_uint4(*(unsigned*)&h0, *(unsigned*)&h1,
                             *(unsigned*)&h2, *(unsigned*)&h3);
        *(uint4*)(out16 + (size_t)n * 64 + sub * 8) = p;
    }
}

// ---------------- classifier --------------------------------------------------
__global__ void k_final(const float* __restrict__ pooled,
                        const int* __restrict__ counts,
                        const float* __restrict__ Wl,
                        const float* __restrict__ bl,
                        float* __restrict__ out) {
    int tid = blockIdx.x * blockDim.x + threadIdx.x;
    if (tid >= N_GRAPHS * N_CLASSES) return;
    int g = tid / N_CLASSES;
    int j = tid - g * N_CLASSES;
    float s = 0.0f;
#pragma unroll
    for (int c = 0; c < 64; c++) s += pooled[g * 64 + c] * Wl[c * N_CLASSES + j];
    float cnt = fmaxf((float)counts[g], 1.0f);
    out[tid] = s / cnt + bl[j];
}

// ---------------- host launch -------------------------------------------------
template <typename T, typename S>
static T* sym_addr(const S& sym) {
    void* p = nullptr;
    cudaGetSymbolAddress(&p, sym);
    return (T*)p;
}

extern "C" void kernel_launch(void* const* d_in, const int* in_sizes, int n_in,
                              void* d_out, int out_size) {
    const float* x     = (const float*)d_in[0];
    const int*   ei    = (const int*)d_in[1];
    const int*   srcp  = ei;
    const int*   dstp  = ei + N_EDGES;
    const int*   batch = (const int*)d_in[3];
    const float* W1 = (const float*)d_in[4];
    const float* b1 = (const float*)d_in[5];
    const float* W2 = (const float*)d_in[6];
    const float* b2 = (const float*)d_in[7];
    const float* Wl = (const float*)d_in[8];
    const float* bl = (const float*)d_in[9];
    float* out = (float*)d_out;

    static int*    p_deg    = nullptr;
    static int*    p_offs   = nullptr;
    static int*    p_cursor = nullptr;
    static int*    p_total  = nullptr;
    static float*  p_dinv   = nullptr;
    static int*    p_csr    = nullptr;
    static __half* p_hw     = nullptr;
    static __half* p_agg1   = nullptr;
    static float*  p_pooled = nullptr;
    static int*    p_counts = nullptr;
    if (!p_deg) {
        p_deg    = sym_addr<int>(g_deg);
        p_offs   = sym_addr<int>(g_offs);
        p_cursor = sym_addr<int>(g_cursor);
        p_total  = sym_addr<int>(g_total);
        p_dinv   = sym_addr<float>(g_dinv);
        p_csr    = sym_addr<int>(g_csr);
        p_hw     = sym_addr<__half>(g_hw);
        p_agg1   = sym_addr<__half>(g_agg1);
        p_pooled = sym_addr<float>(g_pooled);
        p_counts = sym_addr<int>(g_counts);
    }

    const int B = 256;

    // ---- CSR build ----
    k_init<<<(N_NODES + B - 1) / B, B>>>(p_deg, p_pooled, p_counts, p_total);
    k_deg_counts<<<(N_EDGES + B - 1) / B, B>>>(dstp, p_deg, batch, p_counts);
    k_scan<<<N_SCANBLK, SCAN_B>>>(p_deg, p_offs, p_cursor, p_total, p_dinv);
    k_csr<<<(N_EDGES + B - 1) / B, B>>>(srcp, dstp, p_cursor, p_csr);

    // ---- layer 1 ----
    k_gemm_wmma<IN_CH, false><<<(N_NODES + 63) / 64, B>>>(x, W1, p_hw);
    k_agg<true, false><<<(N_NODES * 8 + B - 1) / B, B>>>(
        p_deg, p_offs, p_dinv, p_csr, p_hw, b1, p_agg1, nullptr, nullptr);

    // ---- layer 2 (aggregate fused with mean-pool scatter) ----
    k_gemm_wmma<HID, true><<<(N_NODES + 63) / 64, B>>>(p_agg1, W2, p_hw);
    k_agg<false, true><<<(N_NODES * 8 + B - 1) / B, B>>>(
        p_deg, p_offs, p_dinv, p_csr, p_hw, b2, nullptr, batch, p_pooled);

    // ---- classifier ----
    k_final<<<(N_GRAPHS * N_CLASSES + B - 1) / B, B>>>(p_pooled, p_counts, Wl, bl, out);
}